// round 8
// baseline (speedup 1.0000x reference)
#include <cuda_runtime.h>
#include <math.h>
#include <stdint.h>

#define NUM_B   4
#define SEQ_T   4096
#define NTOK    (NUM_B*SEQ_T)      // 16384
#define MODEL   2048
#define RANK    16
#define DD      1024               // NUM_HEADS * PE_DIM
#define QK_ELEMS 33554432          // NTOK*16*128

typedef unsigned long long ull;

// scratch (allocation-free rule: __device__ globals)
__device__ float g_u[NTOK*RANK];   // x_norm @ W1
__device__ float g_U[NTOK*RANK];   // cumsum over t of g_u

// ---- packed f32x2 helpers (sm_103a FFMA2 path, PTX-only) --------------------
__device__ __forceinline__ ull pk2(float a, float b) {
    ull r;
    asm("mov.b64 %0, {%1, %2};" : "=l"(r) : "f"(a), "f"(b));
    return r;
}
__device__ __forceinline__ void fma2(ull& d, ull a, ull b) {
    asm("fma.rn.f32x2 %0, %1, %2, %0;" : "+l"(d) : "l"(a), "l"(b));
}
__device__ __forceinline__ ull add2(ull a, ull b) {
    ull r;
    asm("add.rn.f32x2 %0, %1, %2;" : "=l"(r) : "l"(a), "l"(b));
    return r;
}
__device__ __forceinline__ float fcomp(float4 v, int i) {
    switch (i) { case 0: return v.x; case 1: return v.y; case 2: return v.z; default: return v.w; }
}

// ---------------------------------------------------------------------------
// Kernel A (v6): fully warp-autonomous. Each warp: 4 tokens, all 16 r.
//   FFMA2 packed over r-PAIRS (native W1 layout has r adjacent).
//   W1 in smem plane layout [(c*4+dd)*8+rp][lane] (ull, conflict-free LDS.64).
//   x: direct LDG.128, depth-2 register prefetch. No cross-warp sync at all.
// ---------------------------------------------------------------------------
#define KA_BLOCKS 128
__global__ __launch_bounds__(512) void kA(const float* __restrict__ hid,
                                          const float* __restrict__ W1)
{
    extern __shared__ float Wsm[];   // 32768 floats = 131072 B
    const int tid  = threadIdx.x;
    const int lane = tid & 31;
    const int wid  = tid >> 5;

    for (int idx = tid; idx < MODEL*RANK; idx += 512) {
        const int d = idx >> 4, r = idx & 15;
        const int c = d >> 7, l = (d >> 2) & 31, dd = d & 3;
        Wsm[((((c << 2) + dd) << 3) + (r >> 1))*64 + l*2 + (r & 1)] = W1[idx];
    }
    __syncthreads();

    const ull* Wsu = (const ull*)Wsm;

    for (int task = blockIdx.x*16 + wid; task < NTOK/4; task += KA_BLOCKS*16) {
        const int tok = task * 4;
        const float* xg = hid + (size_t)tok*MODEL + lane*4;

        float4 xq[2][4];
        #pragma unroll
        for (int pf = 0; pf < 2; ++pf)
            #pragma unroll
            for (int t = 0; t < 4; ++t)
                xq[pf][t] = *(const float4*)(xg + (size_t)t*MODEL + pf*128);

        ull acc[4][8];
        #pragma unroll
        for (int t = 0; t < 4; ++t)
            #pragma unroll
            for (int r = 0; r < 8; ++r) acc[t][r] = 0ull;

        #pragma unroll
        for (int c = 0; c < 16; ++c) {
            const int buf = c & 1;

            float ss[4];
            #pragma unroll
            for (int t = 0; t < 4; ++t) {
                float4 v = xq[buf][t];
                ss[t] = v.x*v.x + v.y*v.y + v.z*v.z + v.w*v.w;
            }
            #pragma unroll
            for (int o = 16; o > 0; o >>= 1) {
                #pragma unroll
                for (int t = 0; t < 4; ++t)
                    ss[t] += __shfl_xor_sync(0xffffffffu, ss[t], o);
            }
            float inv[4];
            #pragma unroll
            for (int t = 0; t < 4; ++t) inv[t] = rsqrtf(ss[t] + 1e-6f);

            const ull* wc = Wsu + c*1024 + lane;
            #pragma unroll
            for (int dd = 0; dd < 4; ++dd) {
                ull xpt[4];
                #pragma unroll
                for (int t = 0; t < 4; ++t) {
                    const float xs = fcomp(xq[buf][t], dd) * inv[t];
                    xpt[t] = pk2(xs, xs);
                }
                const ull* wp = wc + dd*256;
                #pragma unroll
                for (int rp = 0; rp < 8; ++rp) {
                    const ull w = wp[rp*32];
                    #pragma unroll
                    for (int t = 0; t < 4; ++t)
                        fma2(acc[t][rp], xpt[t], w);
                }
            }

            if (c < 14) {
                #pragma unroll
                for (int t = 0; t < 4; ++t)
                    xq[buf][t] = *(const float4*)(xg + (size_t)t*MODEL + (c+2)*128);
            }
        }

        ull v[32];
        #pragma unroll
        for (int t = 0; t < 4; ++t)
            #pragma unroll
            for (int rp = 0; rp < 8; ++rp)
                v[t*8 + rp] = acc[t][rp];

        #pragma unroll
        for (int o = 16; o >= 1; o >>= 1) {
            const bool up = (lane & o) != 0;
            #pragma unroll
            for (int j = 0; j < o; ++j) {
                ull send = up ? v[j] : v[j + o];
                ull keep = up ? v[j + o] : v[j];
                v[j] = add2(keep, __shfl_xor_sync(0xffffffffu, send, o));
            }
        }
        *(ull*)(g_u + (tok + (lane >> 3))*RANK + (lane & 7)*2) = v[0];
    }
}

// ---------------------------------------------------------------------------
// Kernel B: inclusive cumsum over t (per b, per r). grid (16, 4), 1024 threads.
// ---------------------------------------------------------------------------
__global__ __launch_bounds__(1024) void kB()
{
    __shared__ float wsum[32];
    const int r = blockIdx.x, b = blockIdx.y;
    const int tid = threadIdx.x, lane = tid & 31, wid = tid >> 5;
    const float* up = g_u + ((size_t)b*SEQ_T)*RANK + r;
    const int t = tid*4;
    float u0 = up[(t+0)*RANK];
    float u1 = up[(t+1)*RANK];
    float u2 = up[(t+2)*RANK];
    float u3 = up[(t+3)*RANK];
    float v0 = u0, v1 = v0+u1, v2 = v1+u2, v3 = v2+u3;
    float s = v3;
    #pragma unroll
    for (int o = 1; o < 32; o <<= 1) { float n = __shfl_up_sync(0xffffffffu, s, o); if (lane >= o) s += n; }
    if (lane == 31) wsum[wid] = s;
    __syncthreads();
    if (wid == 0) {
        float ws = wsum[lane];
        #pragma unroll
        for (int o = 1; o < 32; o <<= 1) { float n = __shfl_up_sync(0xffffffffu, ws, o); if (lane >= o) ws += n; }
        wsum[lane] = ws;
    }
    __syncthreads();
    const float base = (wid > 0) ? wsum[wid-1] : 0.f;
    const float excl = base + s - v3;
    float* Up = g_U + ((size_t)b*SEQ_T)*RANK + r;
    Up[(t+0)*RANK] = excl + v0;
    Up[(t+1)*RANK] = excl + v1;
    Up[(t+2)*RANK] = excl + v2;
    Up[(t+3)*RANK] = excl + v3;
}

// ---------------------------------------------------------------------------
// Kernel C (v2): sync-free streaming. Depthwise conv never crosses threads,
//   so each thread keeps 3 rolling PD float4s (its own 4 d) in registers,
//   computes each PD row exactly once, convs locally, rotates q & k.
//   Only one __syncthreads (after the tiny Us stage). U rows are read as
//   lane-uniform LDS broadcasts (free). Warps stream fully independently.
// ---------------------------------------------------------------------------
__global__ __launch_bounds__(256, 2) void kC(const float* __restrict__ q,
                                             const float* __restrict__ k,
                                             const float* __restrict__ W2,
                                             const float* __restrict__ cw,
                                             float* __restrict__ out)
{
    __shared__ float Us[67*RANK];
    const int tid  = threadIdx.x;
    const int tok0 = blockIdx.x * 64;
    const int b    = tok0 >> 12;
    const int t0   = tok0 & 4095;

    for (int i = tid; i < 67*RANK; i += 256) {
        const int row = t0 - 3 + (i >> 4);
        Us[i] = (row < 0) ? 0.f : g_U[(((size_t)b << 12) + row)*RANK + (i & 15)];
    }

    const int d0 = tid << 2;
    const int hh = d0 >> 6;
    const size_t qoff0 = (size_t)(hh << 6) + d0;   // h*128 + j0
    const int j0 = d0 & 63;
    const float LNT = 0.20503692775998528f;        // ln(500000)/64
    const float4 tv = make_float4(expf(-LNT*(float)j0),
                                  expf(-LNT*(float)(j0+1)),
                                  expf(-LNT*(float)(j0+2)),
                                  expf(-LNT*(float)(j0+3)));
    float4 w2c[16];
    #pragma unroll
    for (int r = 0; r < 16; ++r) w2c[r] = *(const float4*)(W2 + r*DD + d0);
    float4 cvs[4];
    #pragma unroll
    for (int w = 0; w < 4; ++w) {
        float4 c = *(const float4*)(cw + w*DD + d0);
        cvs[w] = make_float4(c.x*tv.x, c.y*tv.y, c.z*tv.z, c.w*tv.w);
    }
    __syncthreads();

    // PD row for Us row `row` (this thread's 4 d)
    auto pdrow = [&](int row) -> float4 {
        const float* Ur = Us + row*RANK;
        float4 a = make_float4(0.f, 0.f, 0.f, 0.f);
        #pragma unroll
        for (int r = 0; r < 16; ++r) {
            const float u = Ur[r];
            a.x = fmaf(w2c[r].x, u, a.x);
            a.y = fmaf(w2c[r].y, u, a.y);
            a.z = fmaf(w2c[r].z, u, a.z);
            a.w = fmaf(w2c[r].w, u, a.w);
        }
        return a;
    };

    float4 pA = pdrow(0), pB = pdrow(1), pC = pdrow(2);

    #pragma unroll 4
    for (int t = 0; t < 64; ++t) {
        const float4 pD = pdrow(t + 3);

        const float ax = cvs[0].x*pA.x + cvs[1].x*pB.x + cvs[2].x*pC.x + cvs[3].x*pD.x;
        const float ay = cvs[0].y*pA.y + cvs[1].y*pB.y + cvs[2].y*pC.y + cvs[3].y*pD.y;
        const float az = cvs[0].z*pA.z + cvs[1].z*pB.z + cvs[2].z*pC.z + cvs[3].z*pD.z;
        const float aw = cvs[0].w*pA.w + cvs[1].w*pB.w + cvs[2].w*pC.w + cvs[3].w*pD.w;
        float s0, c0, s1, c1, s2, c2, s3, c3;
        __sincosf(ax, &s0, &c0);
        __sincosf(ay, &s1, &c1);
        __sincosf(az, &s2, &c2);
        __sincosf(aw, &s3, &c3);

        const size_t base = (size_t)(tok0 + t)*2048 + qoff0;
        float4 q0 = *(const float4*)(q + base);
        float4 q1 = *(const float4*)(q + base + 64);
        float4 k0 = *(const float4*)(k + base);
        float4 k1 = *(const float4*)(k + base + 64);

        float4 o0, o1;
        o0.x = q0.x*c0 - q1.x*s0;  o1.x = q0.x*s0 + q1.x*c0;
        o0.y = q0.y*c1 - q1.y*s1;  o1.y = q0.y*s1 + q1.y*c1;
        o0.z = q0.z*c2 - q1.z*s2;  o1.z = q0.z*s2 + q1.z*c2;
        o0.w = q0.w*c3 - q1.w*s3;  o1.w = q0.w*s3 + q1.w*c3;
        *(float4*)(out + base)      = o0;
        *(float4*)(out + base + 64) = o1;

        o0.x = k0.x*c0 - k1.x*s0;  o1.x = k0.x*s0 + k1.x*c0;
        o0.y = k0.y*c1 - k1.y*s1;  o1.y = k0.y*s1 + k1.y*c1;
        o0.z = k0.z*c2 - k1.z*s2;  o1.z = k0.z*s2 + k1.z*c2;
        o0.w = k0.w*c3 - k1.w*s3;  o1.w = k0.w*s3 + k1.w*c3;
        *(float4*)(out + QK_ELEMS + base)      = o0;
        *(float4*)(out + QK_ELEMS + base + 64) = o1;

        pA = pB; pB = pC; pC = pD;
    }
}

// ---------------------------------------------------------------------------
extern "C" void kernel_launch(void* const* d_in, const int* in_sizes, int n_in,
                              void* d_out, int out_size)
{
    const float* q   = (const float*)d_in[0];
    const float* k   = (const float*)d_in[1];
    const float* hid = (const float*)d_in[2];
    const float* W1  = (const float*)d_in[3];
    const float* W2  = (const float*)d_in[4];
    const float* cw  = (const float*)d_in[5];
    float* out = (float*)d_out;

    const int SMEM_A = MODEL*RANK*4;                 // 131072 B
    cudaFuncSetAttribute(kA, cudaFuncAttributeMaxDynamicSharedMemorySize, SMEM_A);

    kA<<<KA_BLOCKS, 512, SMEM_A>>>(hid, W1);
    kB<<<dim3(RANK, NUM_B), 1024>>>();
    kC<<<NTOK/64, 256>>>(q, k, W2, cw, out);
}

// round 10
// speedup vs baseline: 1.0081x; 1.0081x over previous
#include <cuda_runtime.h>
#include <math.h>
#include <stdint.h>

#define NUM_B   4
#define SEQ_T   4096
#define NTOK    (NUM_B*SEQ_T)      // 16384
#define MODEL   2048
#define RANK    16
#define DD      1024               // NUM_HEADS * PE_DIM
#define QK_ELEMS 33554432          // NTOK*16*128

typedef unsigned long long ull;

// scratch (allocation-free rule: __device__ globals)
__device__ float g_u[NTOK*RANK];   // x_norm @ W1
__device__ float g_U[NTOK*RANK];   // cumsum over t of g_u

// ---- packed f32x2 helpers (sm_103a FFMA2 path, PTX-only) --------------------
__device__ __forceinline__ ull pk2(float a, float b) {
    ull r;
    asm("mov.b64 %0, {%1, %2};" : "=l"(r) : "f"(a), "f"(b));
    return r;
}
__device__ __forceinline__ void fma2(ull& d, ull a, ull b) {
    asm("fma.rn.f32x2 %0, %1, %2, %0;" : "+l"(d) : "l"(a), "l"(b));
}
__device__ __forceinline__ ull add2(ull a, ull b) {
    ull r;
    asm("add.rn.f32x2 %0, %1, %2;" : "=l"(r) : "l"(a), "l"(b));
    return r;
}
__device__ __forceinline__ float fcomp(float4 v, int i) {
    switch (i) { case 0: return v.x; case 1: return v.y; case 2: return v.z; default: return v.w; }
}

// ---------------------------------------------------------------------------
// Kernel A (v7b): 1024-thread block (32 warps/SM, 8/SMSP), warp = 2 tokens x
//   all 16 r, <=64 regs/thread. FFMA2 over r-pairs, W1 smem plane layout
//   (conflict-free LDS.64), single-buffered x. No cross-warp sync.
//   FIX vs v7: butterfly over 16 values needs the final offset-1 LANE-combine
//   round (4 index rounds only merge 16 of 32 lanes).
// ---------------------------------------------------------------------------
#define KA_BLOCKS 128
__global__ __launch_bounds__(1024) void kA(const float* __restrict__ hid,
                                           const float* __restrict__ W1)
{
    extern __shared__ float Wsm[];   // 32768 floats = 131072 B
    const int tid  = threadIdx.x;
    const int lane = tid & 31;
    const int wid  = tid >> 5;

    // plane layout: word addr = ((c*4+dd)*8 + rp)*64 + l*2 + hi
    // where d = c*128 + l*4 + dd, r = 2*rp + hi   (native W1[d*16 + r])
    for (int idx = tid; idx < MODEL*RANK; idx += 1024) {
        const int d = idx >> 4, r = idx & 15;
        const int c = d >> 7, l = (d >> 2) & 31, dd = d & 3;
        Wsm[((((c << 2) + dd) << 3) + (r >> 1))*64 + l*2 + (r & 1)] = W1[idx];
    }
    __syncthreads();

    const ull* Wsu = (const ull*)Wsm;

    // 8192 two-token tasks; 4096 warps total -> 2 tasks per warp
    for (int task = blockIdx.x*32 + wid; task < NTOK/2; task += KA_BLOCKS*32) {
        const int tok = task * 2;
        const float* xg = hid + (size_t)tok*MODEL + lane*4;

        ull acc[2][8];
        #pragma unroll
        for (int t = 0; t < 2; ++t)
            #pragma unroll
            for (int r = 0; r < 8; ++r) acc[t][r] = 0ull;

        #pragma unroll
        for (int c = 0; c < 16; ++c) {
            float4 xv[2];
            #pragma unroll
            for (int t = 0; t < 2; ++t)
                xv[t] = *(const float4*)(xg + (size_t)t*MODEL + c*128);

            float ss[2];
            #pragma unroll
            for (int t = 0; t < 2; ++t)
                ss[t] = xv[t].x*xv[t].x + xv[t].y*xv[t].y
                      + xv[t].z*xv[t].z + xv[t].w*xv[t].w;
            #pragma unroll
            for (int o = 16; o > 0; o >>= 1) {
                #pragma unroll
                for (int t = 0; t < 2; ++t)
                    ss[t] += __shfl_xor_sync(0xffffffffu, ss[t], o);
            }
            float inv[2];
            #pragma unroll
            for (int t = 0; t < 2; ++t) inv[t] = rsqrtf(ss[t] + 1e-6f);

            const ull* wc = Wsu + c*1024 + lane;
            #pragma unroll
            for (int dd = 0; dd < 4; ++dd) {
                ull xpt[2];
                #pragma unroll
                for (int t = 0; t < 2; ++t) {
                    const float xs = fcomp(xv[t], dd) * inv[t];
                    xpt[t] = pk2(xs, xs);
                }
                const ull* wp = wc + dd*256;
                #pragma unroll
                for (int rp = 0; rp < 8; ++rp) {
                    const ull w = wp[rp*32];
                    #pragma unroll
                    for (int t = 0; t < 2; ++t)
                        fma2(acc[t][rp], xpt[t], w);
                }
            }
        }

        // 4 index-selecting butterfly rounds over 16 values...
        ull v[16];
        #pragma unroll
        for (int t = 0; t < 2; ++t)
            #pragma unroll
            for (int rp = 0; rp < 8; ++rp)
                v[t*8 + rp] = acc[t][rp];

        #pragma unroll
        for (int o = 16; o >= 2; o >>= 1) {
            const int hh = o >> 1;            // surviving half-length
            const bool up = (lane & o) != 0;
            #pragma unroll
            for (int j = 0; j < 8; ++j) {     // bounded by first round
                if (j < hh) {
                    ull send = up ? v[j] : v[j + hh];
                    ull keep = up ? v[j + hh] : v[j];
                    v[j] = add2(keep, __shfl_xor_sync(0xffffffffu, send, o));
                }
            }
        }
        // ...plus the final offset-1 lane combine (no index bit left; lanes
        // l and l^1 hold the same index and must be summed).
        v[0] = add2(v[0], __shfl_xor_sync(0xffffffffu, v[0], 1));

        if (!(lane & 1)) {
            const int t  = (lane >> 4) & 1;
            const int rp = (lane >> 1) & 7;
            *(ull*)(g_u + (tok + t)*RANK + rp*2) = v[0];
        }
    }
}

// ---------------------------------------------------------------------------
// Kernel B: inclusive cumsum over t (per b, per r). grid (16, 4), 1024 threads.
// ---------------------------------------------------------------------------
__global__ __launch_bounds__(1024) void kB()
{
    __shared__ float wsum[32];
    const int r = blockIdx.x, b = blockIdx.y;
    const int tid = threadIdx.x, lane = tid & 31, wid = tid >> 5;
    const float* up = g_u + ((size_t)b*SEQ_T)*RANK + r;
    const int t = tid*4;
    float u0 = up[(t+0)*RANK];
    float u1 = up[(t+1)*RANK];
    float u2 = up[(t+2)*RANK];
    float u3 = up[(t+3)*RANK];
    float v0 = u0, v1 = v0+u1, v2 = v1+u2, v3 = v2+u3;
    float s = v3;
    #pragma unroll
    for (int o = 1; o < 32; o <<= 1) { float n = __shfl_up_sync(0xffffffffu, s, o); if (lane >= o) s += n; }
    if (lane == 31) wsum[wid] = s;
    __syncthreads();
    if (wid == 0) {
        float ws = wsum[lane];
        #pragma unroll
        for (int o = 1; o < 32; o <<= 1) { float n = __shfl_up_sync(0xffffffffu, ws, o); if (lane >= o) ws += n; }
        wsum[lane] = ws;
    }
    __syncthreads();
    const float base = (wid > 0) ? wsum[wid-1] : 0.f;
    const float excl = base + s - v3;
    float* Up = g_U + ((size_t)b*SEQ_T)*RANK + r;
    Up[(t+0)*RANK] = excl + v0;
    Up[(t+1)*RANK] = excl + v1;
    Up[(t+2)*RANK] = excl + v2;
    Up[(t+3)*RANK] = excl + v3;
}

// ---------------------------------------------------------------------------
// Kernel C (R7 version — best measured): PD = W2^T U tiled in smem, reused by
// the 4 conv taps; conv+temp -> angle -> sincos -> rotate q and k.
// 256 blocks x 64 tokens, 256 threads (4 d each).
// ---------------------------------------------------------------------------
__global__ __launch_bounds__(256, 2) void kC(const float* __restrict__ q,
                                             const float* __restrict__ k,
                                             const float* __restrict__ W2,
                                             const float* __restrict__ cw,
                                             float* __restrict__ out)
{
    extern __shared__ float smC[];
    float* PDs = smC;                // [11][1024]
    float* Us  = smC + 11*1024;      // [67][16]
    const int tid  = threadIdx.x;
    const int tok0 = blockIdx.x * 64;
    const int b    = tok0 >> 12;
    const int t0   = tok0 & 4095;

    for (int i = tid; i < 67*RANK; i += 256) {
        const int row = t0 - 3 + (i >> 4);
        Us[i] = (row < 0) ? 0.f : g_U[(((size_t)b << 12) + row)*RANK + (i & 15)];
    }

    const int d0 = tid << 2;
    const int hh = d0 >> 6;
    const size_t qoff0 = (size_t)(hh << 6) + d0;   // h*128 + j0
    const int j0 = d0 & 63;
    const float LNT = 0.20503692775998528f;        // ln(500000)/64
    const float4 tv = make_float4(expf(-LNT*(float)j0),
                                  expf(-LNT*(float)(j0+1)),
                                  expf(-LNT*(float)(j0+2)),
                                  expf(-LNT*(float)(j0+3)));
    float4 w2c[16];
    #pragma unroll
    for (int r = 0; r < 16; ++r) w2c[r] = *(const float4*)(W2 + r*DD + d0);
    float4 cvs[4];
    #pragma unroll
    for (int w = 0; w < 4; ++w) {
        float4 c = *(const float4*)(cw + w*DD + d0);
        cvs[w] = make_float4(c.x*tv.x, c.y*tv.y, c.z*tv.z, c.w*tv.w);
    }
    __syncthreads();

    for (int g = 0; g < 8; ++g) {
        #pragma unroll
        for (int row = 0; row < 11; ++row) {
            const float* Ur = Us + (g*8 + row)*RANK;
            float4 a = make_float4(0.f, 0.f, 0.f, 0.f);
            #pragma unroll
            for (int r = 0; r < 16; ++r) {
                const float u = Ur[r];
                a.x = fmaf(w2c[r].x, u, a.x);
                a.y = fmaf(w2c[r].y, u, a.y);
                a.z = fmaf(w2c[r].z, u, a.z);
                a.w = fmaf(w2c[r].w, u, a.w);
            }
            *(float4*)(PDs + row*DD + d0) = a;
        }
        __syncthreads();

        for (int i = 0; i < 8; ++i) {
            const int tok = tok0 + g*8 + i;
            float4 p0 = *(const float4*)(PDs + (i    )*DD + d0);
            float4 p1 = *(const float4*)(PDs + (i + 1)*DD + d0);
            float4 p2 = *(const float4*)(PDs + (i + 2)*DD + d0);
            float4 p3 = *(const float4*)(PDs + (i + 3)*DD + d0);
            const float ax = cvs[0].x*p0.x + cvs[1].x*p1.x + cvs[2].x*p2.x + cvs[3].x*p3.x;
            const float ay = cvs[0].y*p0.y + cvs[1].y*p1.y + cvs[2].y*p2.y + cvs[3].y*p3.y;
            const float az = cvs[0].z*p0.z + cvs[1].z*p1.z + cvs[2].z*p2.z + cvs[3].z*p3.z;
            const float aw = cvs[0].w*p0.w + cvs[1].w*p1.w + cvs[2].w*p2.w + cvs[3].w*p3.w;
            float s0, c0, s1, c1, s2, c2, s3, c3;
            __sincosf(ax, &s0, &c0);
            __sincosf(ay, &s1, &c1);
            __sincosf(az, &s2, &c2);
            __sincosf(aw, &s3, &c3);

            const size_t base = (size_t)tok*2048 + qoff0;
            float4 q0 = *(const float4*)(q + base);
            float4 q1 = *(const float4*)(q + base + 64);
            float4 k0 = *(const float4*)(k + base);
            float4 k1 = *(const float4*)(k + base + 64);

            float4 o0, o1;
            o0.x = q0.x*c0 - q1.x*s0;  o1.x = q0.x*s0 + q1.x*c0;
            o0.y = q0.y*c1 - q1.y*s1;  o1.y = q0.y*s1 + q1.y*c1;
            o0.z = q0.z*c2 - q1.z*s2;  o1.z = q0.z*s2 + q1.z*c2;
            o0.w = q0.w*c3 - q1.w*s3;  o1.w = q0.w*s3 + q1.w*c3;
            *(float4*)(out + base)      = o0;
            *(float4*)(out + base + 64) = o1;

            o0.x = k0.x*c0 - k1.x*s0;  o1.x = k0.x*s0 + k1.x*c0;
            o0.y = k0.y*c1 - k1.y*s1;  o1.y = k0.y*s1 + k1.y*c1;
            o0.z = k0.z*c2 - k1.z*s2;  o1.z = k0.z*s2 + k1.z*c2;
            o0.w = k0.w*c3 - k1.w*s3;  o1.w = k0.w*s3 + k1.w*c3;
            *(float4*)(out + QK_ELEMS + base)      = o0;
            *(float4*)(out + QK_ELEMS + base + 64) = o1;
        }
        __syncthreads();
    }
}

// ---------------------------------------------------------------------------
extern "C" void kernel_launch(void* const* d_in, const int* in_sizes, int n_in,
                              void* d_out, int out_size)
{
    const float* q   = (const float*)d_in[0];
    const float* k   = (const float*)d_in[1];
    const float* hid = (const float*)d_in[2];
    const float* W1  = (const float*)d_in[3];
    const float* W2  = (const float*)d_in[4];
    const float* cw  = (const float*)d_in[5];
    float* out = (float*)d_out;

    const int SMEM_A = MODEL*RANK*4;                 // 131072 B
    const int SMEM_C = (11*1024 + 67*16) * 4;        // 49344 B
    cudaFuncSetAttribute(kA, cudaFuncAttributeMaxDynamicSharedMemorySize, SMEM_A);
    cudaFuncSetAttribute(kC, cudaFuncAttributeMaxDynamicSharedMemorySize, SMEM_C);

    kA<<<KA_BLOCKS, 1024, SMEM_A>>>(hid, W1);
    kB<<<dim3(RANK, NUM_B), 1024>>>();
    kC<<<NTOK/64, 256, SMEM_C>>>(q, k, W2, cw, out);
}

// round 12
// speedup vs baseline: 1.0373x; 1.0290x over previous
#include <cuda_runtime.h>
#include <math.h>
#include <stdint.h>

#define NUM_B   4
#define SEQ_T   4096
#define NTOK    (NUM_B*SEQ_T)      // 16384
#define MODEL   2048
#define RANK    16
#define DD      1024               // NUM_HEADS * PE_DIM
#define QK_ELEMS 33554432          // NTOK*16*128

typedef unsigned long long ull;

// scratch (allocation-free rule: __device__ globals)
__device__ float g_u[NTOK*RANK];   // x_norm @ W1
__device__ float g_U[NTOK*RANK];   // cumsum over t of g_u

// ---- packed f32x2 helpers (sm_103a FFMA2 path, PTX-only) --------------------
__device__ __forceinline__ ull pk2(float a, float b) {
    ull r;
    asm("mov.b64 %0, {%1, %2};" : "=l"(r) : "f"(a), "f"(b));
    return r;
}
__device__ __forceinline__ void fma2(ull& d, ull a, ull b) {
    asm("fma.rn.f32x2 %0, %1, %2, %0;" : "+l"(d) : "l"(a), "l"(b));
}
__device__ __forceinline__ ull add2(ull a, ull b) {
    ull r;
    asm("add.rn.f32x2 %0, %1, %2;" : "=l"(r) : "l"(a), "l"(b));
    return r;
}
__device__ __forceinline__ float fcomp(float4 v, int i) {
    switch (i) { case 0: return v.x; case 1: return v.y; case 2: return v.z; default: return v.w; }
}

// ---------------------------------------------------------------------------
// Kernel A (R7-exact, best measured 48.6us): warp-autonomous, 4 tokens x 16 r,
//   FFMA2 over r-pairs, W1 smem plane layout, depth-2 register prefetch.
// ---------------------------------------------------------------------------
#define KA_BLOCKS 128
__global__ __launch_bounds__(512) void kA(const float* __restrict__ hid,
                                          const float* __restrict__ W1)
{
    extern __shared__ float Wsm[];   // 32768 floats = 131072 B
    const int tid  = threadIdx.x;
    const int lane = tid & 31;
    const int wid  = tid >> 5;

    for (int idx = tid; idx < MODEL*RANK; idx += 512) {
        const int d = idx >> 4, r = idx & 15;
        const int c = d >> 7, l = (d >> 2) & 31, dd = d & 3;
        Wsm[((((c << 2) + dd) << 3) + (r >> 1))*64 + l*2 + (r & 1)] = W1[idx];
    }
    __syncthreads();

    const ull* Wsu = (const ull*)Wsm;

    for (int task = blockIdx.x*16 + wid; task < NTOK/4; task += KA_BLOCKS*16) {
        const int tok = task * 4;
        const float* xg = hid + (size_t)tok*MODEL + lane*4;

        float4 xq[2][4];
        #pragma unroll
        for (int pf = 0; pf < 2; ++pf)
            #pragma unroll
            for (int t = 0; t < 4; ++t)
                xq[pf][t] = *(const float4*)(xg + (size_t)t*MODEL + pf*128);

        ull acc[4][8];
        #pragma unroll
        for (int t = 0; t < 4; ++t)
            #pragma unroll
            for (int r = 0; r < 8; ++r) acc[t][r] = 0ull;

        #pragma unroll
        for (int c = 0; c < 16; ++c) {
            const int buf = c & 1;

            float ss[4];
            #pragma unroll
            for (int t = 0; t < 4; ++t) {
                float4 v = xq[buf][t];
                ss[t] = v.x*v.x + v.y*v.y + v.z*v.z + v.w*v.w;
            }
            #pragma unroll
            for (int o = 16; o > 0; o >>= 1) {
                #pragma unroll
                for (int t = 0; t < 4; ++t)
                    ss[t] += __shfl_xor_sync(0xffffffffu, ss[t], o);
            }
            float inv[4];
            #pragma unroll
            for (int t = 0; t < 4; ++t) inv[t] = rsqrtf(ss[t] + 1e-6f);

            const ull* wc = Wsu + c*1024 + lane;
            #pragma unroll
            for (int dd = 0; dd < 4; ++dd) {
                ull xpt[4];
                #pragma unroll
                for (int t = 0; t < 4; ++t) {
                    const float xs = fcomp(xq[buf][t], dd) * inv[t];
                    xpt[t] = pk2(xs, xs);
                }
                const ull* wp = wc + dd*256;
                #pragma unroll
                for (int rp = 0; rp < 8; ++rp) {
                    const ull w = wp[rp*32];
                    #pragma unroll
                    for (int t = 0; t < 4; ++t)
                        fma2(acc[t][rp], xpt[t], w);
                }
            }

            if (c < 14) {
                #pragma unroll
                for (int t = 0; t < 4; ++t)
                    xq[buf][t] = *(const float4*)(xg + (size_t)t*MODEL + (c+2)*128);
            }
        }

        ull v[32];
        #pragma unroll
        for (int t = 0; t < 4; ++t)
            #pragma unroll
            for (int rp = 0; rp < 8; ++rp)
                v[t*8 + rp] = acc[t][rp];

        #pragma unroll
        for (int o = 16; o >= 1; o >>= 1) {
            const bool up = (lane & o) != 0;
            #pragma unroll
            for (int j = 0; j < o; ++j) {
                ull send = up ? v[j] : v[j + o];
                ull keep = up ? v[j + o] : v[j];
                v[j] = add2(keep, __shfl_xor_sync(0xffffffffu, send, o));
            }
        }
        *(ull*)(g_u + (tok + (lane >> 3))*RANK + (lane & 7)*2) = v[0];
    }
}

// ---------------------------------------------------------------------------
// Kernel B: inclusive cumsum over t (per b, per r). grid (16, 4), 1024 threads.
// ---------------------------------------------------------------------------
__global__ __launch_bounds__(1024) void kB()
{
    __shared__ float wsum[32];
    const int r = blockIdx.x, b = blockIdx.y;
    const int tid = threadIdx.x, lane = tid & 31, wid = tid >> 5;
    const float* up = g_u + ((size_t)b*SEQ_T)*RANK + r;
    const int t = tid*4;
    float u0 = up[(t+0)*RANK];
    float u1 = up[(t+1)*RANK];
    float u2 = up[(t+2)*RANK];
    float u3 = up[(t+3)*RANK];
    float v0 = u0, v1 = v0+u1, v2 = v1+u2, v3 = v2+u3;
    float s = v3;
    #pragma unroll
    for (int o = 1; o < 32; o <<= 1) { float n = __shfl_up_sync(0xffffffffu, s, o); if (lane >= o) s += n; }
    if (lane == 31) wsum[wid] = s;
    __syncthreads();
    if (wid == 0) {
        float ws = wsum[lane];
        #pragma unroll
        for (int o = 1; o < 32; o <<= 1) { float n = __shfl_up_sync(0xffffffffu, ws, o); if (lane >= o) ws += n; }
        wsum[lane] = ws;
    }
    __syncthreads();
    const float base = (wid > 0) ? wsum[wid-1] : 0.f;
    const float excl = base + s - v3;
    float* Up = g_U + ((size_t)b*SEQ_T)*RANK + r;
    Up[(t+0)*RANK] = excl + v0;
    Up[(t+1)*RANK] = excl + v1;
    Up[(t+2)*RANK] = excl + v2;
    Up[(t+3)*RANK] = excl + v3;
}

// ---------------------------------------------------------------------------
// Kernel C (v3): same phase structure as R7, but 512 threads x 2 d each.
//   Halves per-thread P-phase duration (less memory-idle time) and doubles
//   warps/SM to 32 (occ 50%) for deeper MLP. All accesses float2, coalesced.
// ---------------------------------------------------------------------------
__global__ __launch_bounds__(512, 2) void kC(const float* __restrict__ q,
                                             const float* __restrict__ k,
                                             const float* __restrict__ W2,
                                             const float* __restrict__ cw,
                                             float* __restrict__ out)
{
    extern __shared__ float smC[];
    float* PDs = smC;                // [11][1024]
    float* Us  = smC + 11*1024;      // [67][16]
    const int tid  = threadIdx.x;
    const int tok0 = blockIdx.x * 64;
    const int b    = tok0 >> 12;
    const int t0   = tok0 & 4095;

    for (int i = tid; i < 67*RANK; i += 512) {
        const int row = t0 - 3 + (i >> 4);
        Us[i] = (row < 0) ? 0.f : g_U[(((size_t)b << 12) + row)*RANK + (i & 15)];
    }

    const int d0 = tid << 1;                       // 2 d per thread
    const int hh = d0 >> 6;
    const size_t qoff0 = (size_t)(hh << 6) + d0;   // h*128 + j0
    const int j0 = d0 & 63;
    const float LNT = 0.20503692775998528f;        // ln(500000)/64
    const float2 tv = make_float2(expf(-LNT*(float)j0),
                                  expf(-LNT*(float)(j0+1)));
    float2 w2c[16];
    #pragma unroll
    for (int r = 0; r < 16; ++r) w2c[r] = *(const float2*)(W2 + r*DD + d0);
    float2 cvs[4];
    #pragma unroll
    for (int w = 0; w < 4; ++w) {
        float2 c = *(const float2*)(cw + w*DD + d0);
        cvs[w] = make_float2(c.x*tv.x, c.y*tv.y);
    }
    __syncthreads();

    for (int g = 0; g < 8; ++g) {
        // phase P: PD rows for tokens [g*8-3 .. g*8+7]
        #pragma unroll
        for (int row = 0; row < 11; ++row) {
            const float* Ur = Us + (g*8 + row)*RANK;
            float2 a = make_float2(0.f, 0.f);
            #pragma unroll
            for (int r = 0; r < 16; ++r) {
                const float u = Ur[r];
                a.x = fmaf(w2c[r].x, u, a.x);
                a.y = fmaf(w2c[r].y, u, a.y);
            }
            *(float2*)(PDs + row*DD + d0) = a;
        }
        __syncthreads();

        // phase R: 8 tokens, conv over 4 PD rows -> angle -> sincos -> rotate
        for (int i = 0; i < 8; ++i) {
            const int tok = tok0 + g*8 + i;
            float2 p0 = *(const float2*)(PDs + (i    )*DD + d0);
            float2 p1 = *(const float2*)(PDs + (i + 1)*DD + d0);
            float2 p2 = *(const float2*)(PDs + (i + 2)*DD + d0);
            float2 p3 = *(const float2*)(PDs + (i + 3)*DD + d0);
            const float ax = cvs[0].x*p0.x + cvs[1].x*p1.x + cvs[2].x*p2.x + cvs[3].x*p3.x;
            const float ay = cvs[0].y*p0.y + cvs[1].y*p1.y + cvs[2].y*p2.y + cvs[3].y*p3.y;
            float s0, c0, s1, c1;
            __sincosf(ax, &s0, &c0);
            __sincosf(ay, &s1, &c1);

            const size_t base = (size_t)tok*2048 + qoff0;
            float2 q0 = *(const float2*)(q + base);
            float2 q1 = *(const float2*)(q + base + 64);
            float2 k0 = *(const float2*)(k + base);
            float2 k1 = *(const float2*)(k + base + 64);

            float2 o0, o1;
            o0.x = q0.x*c0 - q1.x*s0;  o1.x = q0.x*s0 + q1.x*c0;
            o0.y = q0.y*c1 - q1.y*s1;  o1.y = q0.y*s1 + q1.y*c1;
            *(float2*)(out + base)      = o0;
            *(float2*)(out + base + 64) = o1;

            o0.x = k0.x*c0 - k1.x*s0;  o1.x = k0.x*s0 + k1.x*c0;
            o0.y = k0.y*c1 - k1.y*s1;  o1.y = k0.y*s1 + k1.y*c1;
            *(float2*)(out + QK_ELEMS + base)      = o0;
            *(float2*)(out + QK_ELEMS + base + 64) = o1;
        }
        __syncthreads();
    }
}

// ---------------------------------------------------------------------------
extern "C" void kernel_launch(void* const* d_in, const int* in_sizes, int n_in,
                              void* d_out, int out_size)
{
    const float* q   = (const float*)d_in[0];
    const float* k   = (const float*)d_in[1];
    const float* hid = (const float*)d_in[2];
    const float* W1  = (const float*)d_in[3];
    const float* W2  = (const float*)d_in[4];
    const float* cw  = (const float*)d_in[5];
    float* out = (float*)d_out;

    const int SMEM_A = MODEL*RANK*4;                 // 131072 B
    const int SMEM_C = (11*1024 + 67*16) * 4;        // 49344 B
    cudaFuncSetAttribute(kA, cudaFuncAttributeMaxDynamicSharedMemorySize, SMEM_A);
    cudaFuncSetAttribute(kC, cudaFuncAttributeMaxDynamicSharedMemorySize, SMEM_C);

    kA<<<KA_BLOCKS, 512, SMEM_A>>>(hid, W1);
    kB<<<dim3(RANK, NUM_B), 1024>>>();
    kC<<<NTOK/64, 512, SMEM_C>>>(q, k, W2, cw, out);
}

// round 13
// speedup vs baseline: 1.0617x; 1.0235x over previous
#include <cuda_runtime.h>
#include <math.h>
#include <stdint.h>

#define NUM_B   4
#define SEQ_T   4096
#define NTOK    (NUM_B*SEQ_T)      // 16384
#define MODEL   2048
#define RANK    16
#define DD      1024               // NUM_HEADS * PE_DIM
#define QK_ELEMS 33554432          // NTOK*16*128

typedef unsigned long long ull;

// scratch (allocation-free rule: __device__ globals)
__device__ float g_u[NTOK*RANK];   // x_norm @ W1
__device__ float g_U[NTOK*RANK];   // cumsum over t of g_u

// ---- packed f32x2 helpers (sm_103a FFMA2 path, PTX-only) --------------------
__device__ __forceinline__ ull pk2(float a, float b) {
    ull r;
    asm("mov.b64 %0, {%1, %2};" : "=l"(r) : "f"(a), "f"(b));
    return r;
}
__device__ __forceinline__ void fma2(ull& d, ull a, ull b) {
    asm("fma.rn.f32x2 %0, %1, %2, %0;" : "+l"(d) : "l"(a), "l"(b));
}
__device__ __forceinline__ ull add2(ull a, ull b) {
    ull r;
    asm("add.rn.f32x2 %0, %1, %2;" : "=l"(r) : "l"(a), "l"(b));
    return r;
}
__device__ __forceinline__ void upk2(ull v, float& a, float& b) {
    asm("mov.b64 {%0, %1}, %2;" : "=f"(a), "=f"(b) : "l"(v));
}
__device__ __forceinline__ float fcomp(float4 v, int i) {
    switch (i) { case 0: return v.x; case 1: return v.y; case 2: return v.z; default: return v.w; }
}

// ---------------------------------------------------------------------------
// Kernel A (R7-exact, best measured 48.1us): warp-autonomous, 4 tokens x 16 r,
//   FFMA2 over r-pairs, W1 smem plane layout, depth-2 register prefetch.
// ---------------------------------------------------------------------------
#define KA_BLOCKS 128
__global__ __launch_bounds__(512) void kA(const float* __restrict__ hid,
                                          const float* __restrict__ W1)
{
    extern __shared__ float Wsm[];   // 32768 floats = 131072 B
    const int tid  = threadIdx.x;
    const int lane = tid & 31;
    const int wid  = tid >> 5;

    for (int idx = tid; idx < MODEL*RANK; idx += 512) {
        const int d = idx >> 4, r = idx & 15;
        const int c = d >> 7, l = (d >> 2) & 31, dd = d & 3;
        Wsm[((((c << 2) + dd) << 3) + (r >> 1))*64 + l*2 + (r & 1)] = W1[idx];
    }
    __syncthreads();

    const ull* Wsu = (const ull*)Wsm;

    for (int task = blockIdx.x*16 + wid; task < NTOK/4; task += KA_BLOCKS*16) {
        const int tok = task * 4;
        const float* xg = hid + (size_t)tok*MODEL + lane*4;

        float4 xq[2][4];
        #pragma unroll
        for (int pf = 0; pf < 2; ++pf)
            #pragma unroll
            for (int t = 0; t < 4; ++t)
                xq[pf][t] = *(const float4*)(xg + (size_t)t*MODEL + pf*128);

        ull acc[4][8];
        #pragma unroll
        for (int t = 0; t < 4; ++t)
            #pragma unroll
            for (int r = 0; r < 8; ++r) acc[t][r] = 0ull;

        #pragma unroll
        for (int c = 0; c < 16; ++c) {
            const int buf = c & 1;

            float ss[4];
            #pragma unroll
            for (int t = 0; t < 4; ++t) {
                float4 v = xq[buf][t];
                ss[t] = v.x*v.x + v.y*v.y + v.z*v.z + v.w*v.w;
            }
            #pragma unroll
            for (int o = 16; o > 0; o >>= 1) {
                #pragma unroll
                for (int t = 0; t < 4; ++t)
                    ss[t] += __shfl_xor_sync(0xffffffffu, ss[t], o);
            }
            float inv[4];
            #pragma unroll
            for (int t = 0; t < 4; ++t) inv[t] = rsqrtf(ss[t] + 1e-6f);

            const ull* wc = Wsu + c*1024 + lane;
            #pragma unroll
            for (int dd = 0; dd < 4; ++dd) {
                ull xpt[4];
                #pragma unroll
                for (int t = 0; t < 4; ++t) {
                    const float xs = fcomp(xq[buf][t], dd) * inv[t];
                    xpt[t] = pk2(xs, xs);
                }
                const ull* wp = wc + dd*256;
                #pragma unroll
                for (int rp = 0; rp < 8; ++rp) {
                    const ull w = wp[rp*32];
                    #pragma unroll
                    for (int t = 0; t < 4; ++t)
                        fma2(acc[t][rp], xpt[t], w);
                }
            }

            if (c < 14) {
                #pragma unroll
                for (int t = 0; t < 4; ++t)
                    xq[buf][t] = *(const float4*)(xg + (size_t)t*MODEL + (c+2)*128);
            }
        }

        ull v[32];
        #pragma unroll
        for (int t = 0; t < 4; ++t)
            #pragma unroll
            for (int rp = 0; rp < 8; ++rp)
                v[t*8 + rp] = acc[t][rp];

        #pragma unroll
        for (int o = 16; o >= 1; o >>= 1) {
            const bool up = (lane & o) != 0;
            #pragma unroll
            for (int j = 0; j < o; ++j) {
                ull send = up ? v[j] : v[j + o];
                ull keep = up ? v[j + o] : v[j];
                v[j] = add2(keep, __shfl_xor_sync(0xffffffffu, send, o));
            }
        }
        *(ull*)(g_u + (tok + (lane >> 3))*RANK + (lane & 7)*2) = v[0];
    }
}

// ---------------------------------------------------------------------------
// Kernel B: inclusive cumsum over t (per b, per r). grid (16, 4), 1024 threads.
// ---------------------------------------------------------------------------
__global__ __launch_bounds__(1024) void kB()
{
    __shared__ float wsum[32];
    const int r = blockIdx.x, b = blockIdx.y;
    const int tid = threadIdx.x, lane = tid & 31, wid = tid >> 5;
    const float* up = g_u + ((size_t)b*SEQ_T)*RANK + r;
    const int t = tid*4;
    float u0 = up[(t+0)*RANK];
    float u1 = up[(t+1)*RANK];
    float u2 = up[(t+2)*RANK];
    float u3 = up[(t+3)*RANK];
    float v0 = u0, v1 = v0+u1, v2 = v1+u2, v3 = v2+u3;
    float s = v3;
    #pragma unroll
    for (int o = 1; o < 32; o <<= 1) { float n = __shfl_up_sync(0xffffffffu, s, o); if (lane >= o) s += n; }
    if (lane == 31) wsum[wid] = s;
    __syncthreads();
    if (wid == 0) {
        float ws = wsum[lane];
        #pragma unroll
        for (int o = 1; o < 32; o <<= 1) { float n = __shfl_up_sync(0xffffffffu, ws, o); if (lane >= o) ws += n; }
        wsum[lane] = ws;
    }
    __syncthreads();
    const float base = (wid > 0) ? wsum[wid-1] : 0.f;
    const float excl = base + s - v3;
    float* Up = g_U + ((size_t)b*SEQ_T)*RANK + r;
    Up[(t+0)*RANK] = excl + v0;
    Up[(t+1)*RANK] = excl + v1;
    Up[(t+2)*RANK] = excl + v2;
    Up[(t+3)*RANK] = excl + v3;
}

// ---------------------------------------------------------------------------
// Kernel C (v4): R7 structure (256 thr x 4 d, PD smem tile, 8 g phases) with
//   the P-phase GEMM and the angle dot product in packed FFMA2 (halves the
//   dominant FFMA issue load: 5632 -> 2816 FFMA2 + 8/token angle FFMA2).
// ---------------------------------------------------------------------------
__global__ __launch_bounds__(256, 2) void kC(const float* __restrict__ q,
                                             const float* __restrict__ k,
                                             const float* __restrict__ W2,
                                             const float* __restrict__ cw,
                                             float* __restrict__ out)
{
    extern __shared__ float smC[];
    float* PDs = smC;                // [11][1024]
    float* Us  = smC + 11*1024;      // [67][16]
    const int tid  = threadIdx.x;
    const int tok0 = blockIdx.x * 64;
    const int b    = tok0 >> 12;
    const int t0   = tok0 & 4095;

    for (int i = tid; i < 67*RANK; i += 256) {
        const int row = t0 - 3 + (i >> 4);
        Us[i] = (row < 0) ? 0.f : g_U[(((size_t)b << 12) + row)*RANK + (i & 15)];
    }

    const int d0 = tid << 2;
    const int hh = d0 >> 6;
    const size_t qoff0 = (size_t)(hh << 6) + d0;   // h*128 + j0
    const int j0 = d0 & 63;
    const float LNT = 0.20503692775998528f;        // ln(500000)/64
    const float tv0 = expf(-LNT*(float)j0);
    const float tv1 = expf(-LNT*(float)(j0+1));
    const float tv2 = expf(-LNT*(float)(j0+2));
    const float tv3 = expf(-LNT*(float)(j0+3));

    // W2 columns packed: per r, (x,y) and (z,w) pairs
    ull w2a[16], w2b[16];
    #pragma unroll
    for (int r = 0; r < 16; ++r) {
        float4 w = *(const float4*)(W2 + r*DD + d0);
        w2a[r] = pk2(w.x, w.y);
        w2b[r] = pk2(w.z, w.w);
    }
    // conv weights (temperature-folded), packed
    ull cva[4], cvb[4];
    #pragma unroll
    for (int w = 0; w < 4; ++w) {
        float4 c = *(const float4*)(cw + w*DD + d0);
        cva[w] = pk2(c.x*tv0, c.y*tv1);
        cvb[w] = pk2(c.z*tv2, c.w*tv3);
    }
    __syncthreads();

    for (int g = 0; g < 8; ++g) {
        // phase P (packed): PD rows for tokens [g*8-3 .. g*8+7]
        #pragma unroll
        for (int row = 0; row < 11; ++row) {
            const float* Ur = Us + (g*8 + row)*RANK;
            ull a01 = 0ull, a23 = 0ull;
            #pragma unroll
            for (int r = 0; r < 16; ++r) {
                const float u = Ur[r];
                const ull uu = pk2(u, u);
                fma2(a01, uu, w2a[r]);
                fma2(a23, uu, w2b[r]);
            }
            ull* dst = (ull*)(PDs + row*DD + d0);
            dst[0] = a01;
            dst[1] = a23;
        }
        __syncthreads();

        // phase R: 8 tokens, packed conv -> angle -> sincos -> rotate
        for (int i = 0; i < 8; ++i) {
            const int tok = tok0 + g*8 + i;
            const ull* p0 = (const ull*)(PDs + (i    )*DD + d0);
            const ull* p1 = (const ull*)(PDs + (i + 1)*DD + d0);
            const ull* p2 = (const ull*)(PDs + (i + 2)*DD + d0);
            const ull* p3 = (const ull*)(PDs + (i + 3)*DD + d0);

            ull aA = 0ull, aB = 0ull;
            fma2(aA, cva[0], p0[0]);  fma2(aB, cvb[0], p0[1]);
            fma2(aA, cva[1], p1[0]);  fma2(aB, cvb[1], p1[1]);
            fma2(aA, cva[2], p2[0]);  fma2(aB, cvb[2], p2[1]);
            fma2(aA, cva[3], p3[0]);  fma2(aB, cvb[3], p3[1]);

            float ax, ay, az, aw;
            upk2(aA, ax, ay);
            upk2(aB, az, aw);

            float s0, c0, s1, c1, s2, c2, s3, c3;
            __sincosf(ax, &s0, &c0);
            __sincosf(ay, &s1, &c1);
            __sincosf(az, &s2, &c2);
            __sincosf(aw, &s3, &c3);

            const size_t base = (size_t)tok*2048 + qoff0;
            float4 q0 = *(const float4*)(q + base);
            float4 q1 = *(const float4*)(q + base + 64);
            float4 k0 = *(const float4*)(k + base);
            float4 k1 = *(const float4*)(k + base + 64);

            float4 o0, o1;
            o0.x = q0.x*c0 - q1.x*s0;  o1.x = q0.x*s0 + q1.x*c0;
            o0.y = q0.y*c1 - q1.y*s1;  o1.y = q0.y*s1 + q1.y*c1;
            o0.z = q0.z*c2 - q1.z*s2;  o1.z = q0.z*s2 + q1.z*c2;
            o0.w = q0.w*c3 - q1.w*s3;  o1.w = q0.w*s3 + q1.w*c3;
            *(float4*)(out + base)      = o0;
            *(float4*)(out + base + 64) = o1;

            o0.x = k0.x*c0 - k1.x*s0;  o1.x = k0.x*s0 + k1.x*c0;
            o0.y = k0.y*c1 - k1.y*s1;  o1.y = k0.y*s1 + k1.y*c1;
            o0.z = k0.z*c2 - k1.z*s2;  o1.z = k0.z*s2 + k1.z*c2;
            o0.w = k0.w*c3 - k1.w*s3;  o1.w = k0.w*s3 + k1.w*c3;
            *(float4*)(out + QK_ELEMS + base)      = o0;
            *(float4*)(out + QK_ELEMS + base + 64) = o1;
        }
        __syncthreads();
    }
}

// ---------------------------------------------------------------------------
extern "C" void kernel_launch(void* const* d_in, const int* in_sizes, int n_in,
                              void* d_out, int out_size)
{
    const float* q   = (const float*)d_in[0];
    const float* k   = (const float*)d_in[1];
    const float* hid = (const float*)d_in[2];
    const float* W1  = (const float*)d_in[3];
    const float* W2  = (const float*)d_in[4];
    const float* cw  = (const float*)d_in[5];
    float* out = (float*)d_out;

    const int SMEM_A = MODEL*RANK*4;                 // 131072 B
    const int SMEM_C = (11*1024 + 67*16) * 4;        // 49344 B
    cudaFuncSetAttribute(kA, cudaFuncAttributeMaxDynamicSharedMemorySize, SMEM_A);
    cudaFuncSetAttribute(kC, cudaFuncAttributeMaxDynamicSharedMemorySize, SMEM_C);

    kA<<<KA_BLOCKS, 512, SMEM_A>>>(hid, W1);
    kB<<<dim3(RANK, NUM_B), 1024>>>();
    kC<<<NTOK/64, 256, SMEM_C>>>(q, k, W2, cw, out);
}

// round 16
// speedup vs baseline: 1.0752x; 1.0128x over previous
#include <cuda_runtime.h>
#include <math.h>
#include <stdint.h>

#define NUM_B   4
#define SEQ_T   4096
#define NTOK    (NUM_B*SEQ_T)      // 16384
#define MODEL   2048
#define RANK    16
#define DD      1024               // NUM_HEADS * PE_DIM
#define QK_ELEMS 33554432          // NTOK*16*128

typedef unsigned long long ull;

// scratch (allocation-free rule: __device__ globals)
__device__ float g_u[NTOK*RANK];   // x_norm @ W1
__device__ float g_U[NTOK*RANK];   // cumsum over t of g_u

// ---- packed f32x2 helpers (sm_103a FFMA2 path, PTX-only) --------------------
__device__ __forceinline__ ull pk2(float a, float b) {
    ull r;
    asm("mov.b64 %0, {%1, %2};" : "=l"(r) : "f"(a), "f"(b));
    return r;
}
__device__ __forceinline__ void fma2(ull& d, ull a, ull b) {
    asm("fma.rn.f32x2 %0, %1, %2, %0;" : "+l"(d) : "l"(a), "l"(b));
}
__device__ __forceinline__ ull add2(ull a, ull b) {
    ull r;
    asm("add.rn.f32x2 %0, %1, %2;" : "=l"(r) : "l"(a), "l"(b));
    return r;
}
__device__ __forceinline__ void upk2(ull v, float& a, float& b) {
    asm("mov.b64 {%0, %1}, %2;" : "=f"(a), "=f"(b) : "l"(v));
}
__device__ __forceinline__ float fcomp(float4 v, int i) {
    switch (i) { case 0: return v.x; case 1: return v.y; case 2: return v.z; default: return v.w; }
}
// streaming (evict-first) 128-bit load/store
__device__ __forceinline__ float4 ldcs4(const float* p) {
    float4 v;
    asm volatile("ld.global.cs.v4.f32 {%0,%1,%2,%3}, [%4];"
                 : "=f"(v.x), "=f"(v.y), "=f"(v.z), "=f"(v.w) : "l"(p));
    return v;
}
__device__ __forceinline__ void stcs4(float* p, float4 v) {
    asm volatile("st.global.cs.v4.f32 [%0], {%1,%2,%3,%4};"
                 :: "l"(p), "f"(v.x), "f"(v.y), "f"(v.z), "f"(v.w) : "memory");
}

// ---------------------------------------------------------------------------
// Kernel A (R7 structure + streaming loads): warp-autonomous, 4 tokens x 16 r,
//   FFMA2 over r-pairs, W1 smem plane layout, depth-2 register prefetch.
// ---------------------------------------------------------------------------
#define KA_BLOCKS 128
__global__ __launch_bounds__(512) void kA(const float* __restrict__ hid,
                                          const float* __restrict__ W1)
{
    extern __shared__ float Wsm[];   // 32768 floats = 131072 B
    const int tid  = threadIdx.x;
    const int lane = tid & 31;
    const int wid  = tid >> 5;

    for (int idx = tid; idx < MODEL*RANK; idx += 512) {
        const int d = idx >> 4, r = idx & 15;
        const int c = d >> 7, l = (d >> 2) & 31, dd = d & 3;
        Wsm[((((c << 2) + dd) << 3) + (r >> 1))*64 + l*2 + (r & 1)] = W1[idx];
    }
    __syncthreads();

    const ull* Wsu = (const ull*)Wsm;

    for (int task = blockIdx.x*16 + wid; task < NTOK/4; task += KA_BLOCKS*16) {
        const int tok = task * 4;
        const float* xg = hid + (size_t)tok*MODEL + lane*4;

        float4 xq[2][4];
        #pragma unroll
        for (int pf = 0; pf < 2; ++pf)
            #pragma unroll
            for (int t = 0; t < 4; ++t)
                xq[pf][t] = ldcs4(xg + (size_t)t*MODEL + pf*128);

        ull acc[4][8];
        #pragma unroll
        for (int t = 0; t < 4; ++t)
            #pragma unroll
            for (int r = 0; r < 8; ++r) acc[t][r] = 0ull;

        #pragma unroll
        for (int c = 0; c < 16; ++c) {
            const int buf = c & 1;

            float ss[4];
            #pragma unroll
            for (int t = 0; t < 4; ++t) {
                float4 v = xq[buf][t];
                ss[t] = v.x*v.x + v.y*v.y + v.z*v.z + v.w*v.w;
            }
            #pragma unroll
            for (int o = 16; o > 0; o >>= 1) {
                #pragma unroll
                for (int t = 0; t < 4; ++t)
                    ss[t] += __shfl_xor_sync(0xffffffffu, ss[t], o);
            }
            float inv[4];
            #pragma unroll
            for (int t = 0; t < 4; ++t) inv[t] = rsqrtf(ss[t] + 1e-6f);

            const ull* wc = Wsu + c*1024 + lane;
            #pragma unroll
            for (int dd = 0; dd < 4; ++dd) {
                ull xpt[4];
                #pragma unroll
                for (int t = 0; t < 4; ++t) {
                    const float xs = fcomp(xq[buf][t], dd) * inv[t];
                    xpt[t] = pk2(xs, xs);
                }
                const ull* wp = wc + dd*256;
                #pragma unroll
                for (int rp = 0; rp < 8; ++rp) {
                    const ull w = wp[rp*32];
                    #pragma unroll
                    for (int t = 0; t < 4; ++t)
                        fma2(acc[t][rp], xpt[t], w);
                }
            }

            if (c < 14) {
                #pragma unroll
                for (int t = 0; t < 4; ++t)
                    xq[buf][t] = ldcs4(xg + (size_t)t*MODEL + (c+2)*128);
            }
        }

        ull v[32];
        #pragma unroll
        for (int t = 0; t < 4; ++t)
            #pragma unroll
            for (int rp = 0; rp < 8; ++rp)
                v[t*8 + rp] = acc[t][rp];

        #pragma unroll
        for (int o = 16; o >= 1; o >>= 1) {
            const bool up = (lane & o) != 0;
            #pragma unroll
            for (int j = 0; j < o; ++j) {
                ull send = up ? v[j] : v[j + o];
                ull keep = up ? v[j + o] : v[j];
                v[j] = add2(keep, __shfl_xor_sync(0xffffffffu, send, o));
            }
        }
        *(ull*)(g_u + (tok + (lane >> 3))*RANK + (lane & 7)*2) = v[0];
    }
}

// ---------------------------------------------------------------------------
// Kernel B: inclusive cumsum over t (per b, per r). grid (16, 4), 1024 threads.
// ---------------------------------------------------------------------------
__global__ __launch_bounds__(1024) void kB()
{
    __shared__ float wsum[32];
    const int r = blockIdx.x, b = blockIdx.y;
    const int tid = threadIdx.x, lane = tid & 31, wid = tid >> 5;
    const float* up = g_u + ((size_t)b*SEQ_T)*RANK + r;
    const int t = tid*4;
    float u0 = up[(t+0)*RANK];
    float u1 = up[(t+1)*RANK];
    float u2 = up[(t+2)*RANK];
    float u3 = up[(t+3)*RANK];
    float v0 = u0, v1 = v0+u1, v2 = v1+u2, v3 = v2+u3;
    float s = v3;
    #pragma unroll
    for (int o = 1; o < 32; o <<= 1) { float n = __shfl_up_sync(0xffffffffu, s, o); if (lane >= o) s += n; }
    if (lane == 31) wsum[wid] = s;
    __syncthreads();
    if (wid == 0) {
        float ws = wsum[lane];
        #pragma unroll
        for (int o = 1; o < 32; o <<= 1) { float n = __shfl_up_sync(0xffffffffu, ws, o); if (lane >= o) ws += n; }
        wsum[lane] = ws;
    }
    __syncthreads();
    const float base = (wid > 0) ? wsum[wid-1] : 0.f;
    const float excl = base + s - v3;
    float* Up = g_U + ((size_t)b*SEQ_T)*RANK + r;
    Up[(t+0)*RANK] = excl + v0;
    Up[(t+1)*RANK] = excl + v1;
    Up[(t+2)*RANK] = excl + v2;
    Up[(t+3)*RANK] = excl + v3;
}

// ---------------------------------------------------------------------------
// Kernel C (v5): 512 blocks x 32 tokens (finer phases for better cross-block
//   overlap at 2 blocks/SM), packed-FFMA2 P-phase and angle dot, streaming
//   cache hints on all q/k/out traffic.
// ---------------------------------------------------------------------------
__global__ __launch_bounds__(256, 2) void kC(const float* __restrict__ q,
                                             const float* __restrict__ k,
                                             const float* __restrict__ W2,
                                             const float* __restrict__ cw,
                                             float* __restrict__ out)
{
    extern __shared__ float smC[];
    float* PDs = smC;                // [11][1024]
    float* Us  = smC + 11*1024;      // [35][16]
    const int tid  = threadIdx.x;
    const int tok0 = blockIdx.x * 32;
    const int b    = tok0 >> 12;
    const int t0   = tok0 & 4095;

    for (int i = tid; i < 35*RANK; i += 256) {
        const int row = t0 - 3 + (i >> 4);
        Us[i] = (row < 0) ? 0.f : g_U[(((size_t)b << 12) + row)*RANK + (i & 15)];
    }

    const int d0 = tid << 2;
    const int hh = d0 >> 6;
    const size_t qoff0 = (size_t)(hh << 6) + d0;   // h*128 + j0
    const int j0 = d0 & 63;
    const float LNT = 0.20503692775998528f;        // ln(500000)/64
    const float tv0 = expf(-LNT*(float)j0);
    const float tv1 = expf(-LNT*(float)(j0+1));
    const float tv2 = expf(-LNT*(float)(j0+2));
    const float tv3 = expf(-LNT*(float)(j0+3));

    ull w2a[16], w2b[16];
    #pragma unroll
    for (int r = 0; r < 16; ++r) {
        float4 w = *(const float4*)(W2 + r*DD + d0);
        w2a[r] = pk2(w.x, w.y);
        w2b[r] = pk2(w.z, w.w);
    }
    ull cva[4], cvb[4];
    #pragma unroll
    for (int w = 0; w < 4; ++w) {
        float4 c = *(const float4*)(cw + w*DD + d0);
        cva[w] = pk2(c.x*tv0, c.y*tv1);
        cvb[w] = pk2(c.z*tv2, c.w*tv3);
    }
    __syncthreads();

    for (int g = 0; g < 4; ++g) {
        // phase P (packed FFMA2): PD rows for tokens [g*8-3 .. g*8+7]
        #pragma unroll
        for (int row = 0; row < 11; ++row) {
            const float* Ur = Us + (g*8 + row)*RANK;
            ull a01 = 0ull, a23 = 0ull;
            #pragma unroll
            for (int r = 0; r < 16; ++r) {
                const float u = Ur[r];
                const ull uu = pk2(u, u);
                fma2(a01, uu, w2a[r]);
                fma2(a23, uu, w2b[r]);
            }
            ull* dst = (ull*)(PDs + row*DD + d0);
            dst[0] = a01;
            dst[1] = a23;
        }
        __syncthreads();

        // phase R: 8 tokens, packed conv -> angle -> sincos -> rotate
        for (int i = 0; i < 8; ++i) {
            const int tok = tok0 + g*8 + i;
            const ull* p0 = (const ull*)(PDs + (i    )*DD + d0);
            const ull* p1 = (const ull*)(PDs + (i + 1)*DD + d0);
            const ull* p2 = (const ull*)(PDs + (i + 2)*DD + d0);
            const ull* p3 = (const ull*)(PDs + (i + 3)*DD + d0);

            ull aA = 0ull, aB = 0ull;
            fma2(aA, cva[0], p0[0]);  fma2(aB, cvb[0], p0[1]);
            fma2(aA, cva[1], p1[0]);  fma2(aB, cvb[1], p1[1]);
            fma2(aA, cva[2], p2[0]);  fma2(aB, cvb[2], p2[1]);
            fma2(aA, cva[3], p3[0]);  fma2(aB, cvb[3], p3[1]);

            float ax, ay, az, aw;
            upk2(aA, ax, ay);
            upk2(aB, az, aw);

            float s0, c0, s1, c1, s2, c2, s3, c3;
            __sincosf(ax, &s0, &c0);
            __sincosf(ay, &s1, &c1);
            __sincosf(az, &s2, &c2);
            __sincosf(aw, &s3, &c3);

            const size_t base = (size_t)tok*2048 + qoff0;
            float4 q0 = ldcs4(q + base);
            float4 q1 = ldcs4(q + base + 64);
            float4 k0 = ldcs4(k + base);
            float4 k1 = ldcs4(k + base + 64);

            float4 o0, o1;
            o0.x = q0.x*c0 - q1.x*s0;  o1.x = q0.x*s0 + q1.x*c0;
            o0.y = q0.y*c1 - q1.y*s1;  o1.y = q0.y*s1 + q1.y*c1;
            o0.z = q0.z*c2 - q1.z*s2;  o1.z = q0.z*s2 + q1.z*c2;
            o0.w = q0.w*c3 - q1.w*s3;  o1.w = q0.w*s3 + q1.w*c3;
            stcs4(out + base,      o0);
            stcs4(out + base + 64, o1);

            o0.x = k0.x*c0 - k1.x*s0;  o1.x = k0.x*s0 + k1.x*c0;
            o0.y = k0.y*c1 - k1.y*s1;  o1.y = k0.y*s1 + k1.y*c1;
            o0.z = k0.z*c2 - k1.z*s2;  o1.z = k0.z*s2 + k1.z*c2;
            o0.w = k0.w*c3 - k1.w*s3;  o1.w = k0.w*s3 + k1.w*c3;
            stcs4(out + QK_ELEMS + base,      o0);
            stcs4(out + QK_ELEMS + base + 64, o1);
        }
        __syncthreads();
    }
}

// ---------------------------------------------------------------------------
extern "C" void kernel_launch(void* const* d_in, const int* in_sizes, int n_in,
                              void* d_out, int out_size)
{
    const float* q   = (const float*)d_in[0];
    const float* k   = (const float*)d_in[1];
    const float* hid = (const float*)d_in[2];
    const float* W1  = (const float*)d_in[3];
    const float* W2  = (const float*)d_in[4];
    const float* cw  = (const float*)d_in[5];
    float* out = (float*)d_out;

    const int SMEM_A = MODEL*RANK*4;                 // 131072 B
    const int SMEM_C = (11*1024 + 35*16) * 4;        // 47296 B
    cudaFuncSetAttribute(kA, cudaFuncAttributeMaxDynamicSharedMemorySize, SMEM_A);
    cudaFuncSetAttribute(kC, cudaFuncAttributeMaxDynamicSharedMemorySize, SMEM_C);

    kA<<<KA_BLOCKS, 512, SMEM_A>>>(hid, W1);
    kB<<<dim3(RANK, NUM_B), 1024>>>();
    kC<<<NTOK/32, 256, SMEM_C>>>(q, k, W2, cw, out);
}